// round 5
// baseline (speedup 1.0000x reference)
#include <cuda_runtime.h>
#include <cuda_bf16.h>

// ---------------------------------------------------------------------------
// MS-SSIM loss, 3 scales, 11x11 separable Gaussian (sigma=1.5), zero padding.
// R5: horizontal blur in runs of 6 (sliding window amortization, warp-
//     specialized short runs), vectorized LDG.64 interior tile loads with
//     x-origin shifted to 8B alignment (SPITCH 44).
// ---------------------------------------------------------------------------

#define TILE   32
#define HALO   5
#define LDIM   42            // TILE + 2*HALO
#define SPITCH 44            // raw tile pitch (bf16x2 units), origin x0-6

__device__ constexpr float GWC[11] = {
    0.00102838f, 0.00759875f, 0.03600077f, 0.10936069f, 0.21300553f,
    0.26601173f, 0.21300553f, 0.10936069f, 0.03600077f, 0.00759875f,
    0.00102838f
};

#define C1_ 0.0001f
#define C2_ 0.0009f

typedef unsigned long long u64;

__device__ __forceinline__ u64 pack2(float a, float b) {
    u64 r; asm("mov.b64 %0, {%1, %2};" : "=l"(r) : "f"(a), "f"(b)); return r;
}
__device__ __forceinline__ void unpack2(u64 v, float& a, float& b) {
    asm("mov.b64 {%0, %1}, %2;" : "=f"(a), "=f"(b) : "l"(v));
}
__device__ __forceinline__ u64 fma2(u64 a, u64 b, u64 c) {
    u64 d; asm("fma.rn.f32x2 %0, %1, %2, %3;" : "=l"(d) : "l"(a), "l"(b), "l"(c)); return d;
}
__device__ __forceinline__ u64 mul2(u64 a, u64 b) {
    u64 d; asm("mul.rn.f32x2 %0, %1, %2;" : "=l"(d) : "l"(a), "l"(b)); return d;
}
// bf16x2 -> two fp32 via pure bit ops (exact)
__device__ __forceinline__ void bf2dec(unsigned v, float& a, float& b) {
    a = __int_as_float((int)(v << 16));
    b = __int_as_float((int)(v & 0xffff0000u));
}

// Pooled pyramids (allocation-free device globals), bf16x2 (pred, target)
__device__ __nv_bfloat162 g_s1[64 * 256 * 256];
__device__ __nv_bfloat162 g_s2[64 * 128 * 128];
__device__ double g_acc[3];   // zero-initialized at load; reset by finalize

// ---------------------------------------------------------------------------
// Phases 3-5: horizontal blur (runs of 6 + short runs), vertical blur + SSIM,
// reduction. Output col c taps sxy cols c+1 .. c+11 (x origin is x0-6).
// ---------------------------------------------------------------------------
__device__ __forceinline__ void phases345(
    __nv_bfloat162 (&sxy)[LDIM][SPITCH],
    ulonglong2 (&pAB)[LDIM][TILE],
    float (&p4)[LDIM][TILE],
    float (&red)[8],
    int tx, int ty, int tid, int sidx)
{
    u64 wp[11];
    #pragma unroll
    for (int k = 0; k < 11; k++) wp[k] = pack2(GWC[k], GWC[k]);

    // ---- horizontal blur ----
    if (tid < 210) {
        // full runs of 6: rows 0..41, col groups {0,6,12,18,24}
        const int row = tid / 5;
        const int c0  = (tid - row * 5) * 6;
        const unsigned* rp = (const unsigned*)&sxy[row][0] + (c0 + 1);
        u64 hxy[6] = {0,0,0,0,0,0};
        u64 hsq[6] = {0,0,0,0,0,0};
        float hab[6] = {0.f,0.f,0.f,0.f,0.f,0.f};
        #pragma unroll
        for (int k = 0; k < 16; k++) {
            unsigned v = rp[k];
            float a, b; bf2dec(v, a, b);
            u64 p  = pack2(a, b);
            u64 sq = mul2(p, p);
            float ab = a * b;
            #pragma unroll
            for (int j = 0; j < 6; j++) {
                const int kk = k - j;
                if (kk >= 0 && kk < 11) {
                    hxy[j] = fma2(p,  wp[kk], hxy[j]);
                    hsq[j] = fma2(sq, wp[kk], hsq[j]);
                    hab[j] = fmaf(ab, GWC[kk], hab[j]);
                }
            }
        }
        #pragma unroll
        for (int j = 0; j < 6; j++)
            pAB[row][c0 + j] = make_ulonglong2(hxy[j], hsq[j]);
        #pragma unroll
        for (int j = 0; j < 6; j += 2)
            *(float2*)&p4[row][c0 + j] = make_float2(hab[j], hab[j + 1]);
    } else if (tid >= 224) {
        // warp 7: short runs (cols 30,31) for all 42 rows
        const int lane = tid - 224;
        #pragma unroll
        for (int t = 0; t < 2; t++) {
            const int row = lane + t * 32;
            if (row < 42) {
                const unsigned* rp = (const unsigned*)&sxy[row][0] + 31;
                u64 hxy0 = 0, hsq0 = 0, hxy1 = 0, hsq1 = 0;
                float hab0 = 0.f, hab1 = 0.f;
                #pragma unroll
                for (int k = 0; k < 12; k++) {
                    unsigned v = rp[k];
                    float a, b; bf2dec(v, a, b);
                    u64 p  = pack2(a, b);
                    u64 sq = mul2(p, p);
                    float ab = a * b;
                    if (k < 11) {
                        hxy0 = fma2(p,  wp[k], hxy0);
                        hsq0 = fma2(sq, wp[k], hsq0);
                        hab0 = fmaf(ab, GWC[k], hab0);
                    }
                    if (k > 0) {
                        hxy1 = fma2(p,  wp[k - 1], hxy1);
                        hsq1 = fma2(sq, wp[k - 1], hsq1);
                        hab1 = fmaf(ab, GWC[k - 1], hab1);
                    }
                }
                pAB[row][30] = make_ulonglong2(hxy0, hsq0);
                pAB[row][31] = make_ulonglong2(hxy1, hsq1);
                *(float2*)&p4[row][30] = make_float2(hab0, hab1);
            }
        }
    }
    __syncthreads();

    // ---- vertical blur + SSIM: 4 output rows per thread, 1 col ----
    u64   mA[4] = {0, 0, 0, 0};
    u64   mB[4] = {0, 0, 0, 0};
    float mC[4] = {0.f, 0.f, 0.f, 0.f};
    const int rbase = ty * 4;
    #pragma unroll
    for (int k = 0; k < 14; k++) {
        const int hr = rbase + k;
        ulonglong2 vab = pAB[hr][tx];          // LDS.128
        float v4 = p4[hr][tx];
        #pragma unroll
        for (int j = 0; j < 4; j++) {
            const int kk = k - j;
            if (kk >= 0 && kk < 11) {
                mA[j] = fma2(vab.x, wp[kk], mA[j]);
                mB[j] = fma2(vab.y, wp[kk], mB[j]);
                mC[j] = fmaf(v4, GWC[kk], mC[j]);
            }
        }
    }

    float acc = 0.0f;
    #pragma unroll
    for (int j = 0; j < 4; j++) {
        float mu1, mu2, exx, eyy;
        unpack2(mA[j], mu1, mu2);
        unpack2(mB[j], exx, eyy);
        float mu1sq = mu1 * mu1;
        float mu2sq = mu2 * mu2;
        float mu12  = mu1 * mu2;
        float s1  = exx - mu1sq;
        float s2  = eyy - mu2sq;
        float s12 = mC[j] - mu12;
        float num = (2.0f * mu12 + C1_) * (2.0f * s12 + C2_);
        float den = (mu1sq + mu2sq + C1_) * (s1 + s2 + C2_);
        acc += __fdividef(num, den);
    }

    #pragma unroll
    for (int o = 16; o > 0; o >>= 1)
        acc += __shfl_down_sync(0xffffffffu, acc, o);
    if ((tid & 31) == 0) red[tid >> 5] = acc;
    __syncthreads();
    if (tid < 8) {
        float v = red[tid];
        #pragma unroll
        for (int o = 4; o > 0; o >>= 1)
            v += __shfl_down_sync(0xffu, v, o, 8);
        if (tid == 0) atomicAdd(&g_acc[sidx], (double)v);
    }
}

// ---------------------------------------------------------------------------
// Scale 0: fp32 global inputs, writes BOTH pooled pyramids, then SSIM.
// ---------------------------------------------------------------------------
__global__ __launch_bounds__(256, 5)
void ssim_scale0_kernel(const float* __restrict__ pin, const float* __restrict__ tin)
{
    __shared__ __nv_bfloat162 sxy[LDIM][SPITCH];
    __shared__ ulonglong2 pAB[LDIM][TILE];
    __shared__ float p4[LDIM][TILE];
    __shared__ float red[8];

    const int tx = threadIdx.x, ty = threadIdx.y;
    const int tid = ty * 32 + tx;
    const int x0 = blockIdx.x * TILE;
    const int y0 = blockIdx.y * TILE;
    const int H = 512, W = 512;
    const long imgBase = (long)blockIdx.z * H * W;

    const bool interior = (x0 >= 8) && (x0 + 40 <= W) &&
                          (y0 >= 8) && (y0 + 40 <= H);
    if (interior) {
        // 42 rows x 22 float2 loads (x origin x0-6, 8B aligned)
        const float* pb = pin + imgBase + (long)(y0 - 5) * W + (x0 - 6);
        const float* tb = tin + imgBase + (long)(y0 - 5) * W + (x0 - 6);
        #pragma unroll
        for (int it = 0; it < 4; it++) {
            const int i = tid + it * 256;
            if (i < 924) {
                const int r = i / 22, c2 = i - r * 22;
                float2 av = __ldg((const float2*)(pb + (long)r * W) + c2);
                float2 bv = __ldg((const float2*)(tb + (long)r * W) + c2);
                __nv_bfloat162 t0 = __floats2bfloat162_rn(av.x, bv.x);
                __nv_bfloat162 t1 = __floats2bfloat162_rn(av.y, bv.y);
                *(uint2*)&sxy[r][2 * c2] =
                    make_uint2(*(unsigned*)&t0, *(unsigned*)&t1);
            }
        }
    } else {
        #pragma unroll
        for (int i = tid; i < LDIM * SPITCH; i += 256) {
            int r = i / SPITCH, c = i - r * SPITCH;
            int gy = y0 + r - 5;
            int gx = x0 + c - 6;
            float a = 0.0f, b = 0.0f;
            if (gy >= 0 && gy < H && gx >= 0 && gx < W) {
                long off = imgBase + (long)gy * W + gx;
                a = __ldg(pin + off);
                b = __ldg(tin + off);
            }
            sxy[r][c] = __floats2bfloat162_rn(a, b);
        }
    }
    __syncthreads();

    // 2x2 pool -> g_s1 (one output px per thread: 16x16)
    {
        const int pr = tid >> 4;
        const int pc = tid & 15;
        const int r = 5 + 2 * pr, c = 6 + 2 * pc;
        float a0, b0, a1, b1, a2, b2, a3, b3;
        bf2dec(*(const unsigned*)&sxy[r][c],         a0, b0);
        bf2dec(*(const unsigned*)&sxy[r][c + 1],     a1, b1);
        bf2dec(*(const unsigned*)&sxy[r + 1][c],     a2, b2);
        bf2dec(*(const unsigned*)&sxy[r + 1][c + 1], a3, b3);
        float a = 0.25f * (a0 + a1 + a2 + a3);
        float b = 0.25f * (b0 + b1 + b2 + b3);
        long poff = (long)blockIdx.z * 256 * 256
                  + (long)(y0 / 2 + pr) * 256 + (x0 / 2 + pc);
        g_s1[poff] = __floats2bfloat162_rn(a, b);
    }
    // 4x4 pool -> g_s2 (8x8 outputs per tile, threads 0..63)
    if (tid < 64) {
        const int pr = tid >> 3;
        const int pc = tid & 7;
        const int r = 5 + 4 * pr, c = 6 + 4 * pc;
        float sa = 0.f, sb = 0.f;
        #pragma unroll
        for (int dr = 0; dr < 4; dr++)
            #pragma unroll
            for (int dc = 0; dc < 4; dc++) {
                float a, b;
                bf2dec(*(const unsigned*)&sxy[r + dr][c + dc], a, b);
                sa += a; sb += b;
            }
        long poff = (long)blockIdx.z * 128 * 128
                  + (long)(y0 / 4 + pr) * 128 + (x0 / 4 + pc);
        g_s2[poff] = __floats2bfloat162_rn(sa * 0.0625f, sb * 0.0625f);
    }

    phases345(sxy, pAB, p4, red, tx, ty, tid, 0);
}

// ---------------------------------------------------------------------------
// Scales 1+2 merged: z < 64 -> scale1 (256x256), z >= 64 -> scale2 (128x128).
// ---------------------------------------------------------------------------
__global__ __launch_bounds__(256, 5)
void ssim_small_kernel()
{
    __shared__ __nv_bfloat162 sxy[LDIM][SPITCH];
    __shared__ ulonglong2 pAB[LDIM][TILE];
    __shared__ float p4[LDIM][TILE];
    __shared__ float red[8];

    const int tx = threadIdx.x, ty = threadIdx.y;
    const int tid = ty * 32 + tx;
    const int z = blockIdx.z;

    const __nv_bfloat162* src;
    int x0, y0, img, H, sidx;
    if (z < 64) {
        src = g_s1; H = 256; sidx = 1;
        x0 = blockIdx.x * TILE; y0 = blockIdx.y * TILE; img = z;
    } else {
        src = g_s2; H = 128; sidx = 2;
        const int z2 = z - 64;
        img = z2 * 4 + ((blockIdx.y >> 2) << 1) + (blockIdx.x >> 2);
        x0 = (blockIdx.x & 3) * TILE;
        y0 = (blockIdx.y & 3) * TILE;
    }
    const int W = H;
    const long imgBase = (long)img * H * W;

    const bool interior = (x0 >= 8) && (x0 + 40 <= W) &&
                          (y0 >= 8) && (y0 + 40 <= H);
    if (interior) {
        const __nv_bfloat162* sb = src + imgBase + (long)(y0 - 5) * W + (x0 - 6);
        #pragma unroll
        for (int it = 0; it < 4; it++) {
            const int i = tid + it * 256;
            if (i < 924) {
                const int r = i / 22, c2 = i - r * 22;
                uint2 v = __ldg((const uint2*)(sb + (long)r * W) + c2);
                *(uint2*)&sxy[r][2 * c2] = v;
            }
        }
    } else {
        #pragma unroll
        for (int i = tid; i < LDIM * SPITCH; i += 256) {
            int r = i / SPITCH, c = i - r * SPITCH;
            int gy = y0 + r - 5;
            int gx = x0 + c - 6;
            __nv_bfloat162 v; *(unsigned*)&v = 0u;
            if (gy >= 0 && gy < H && gx >= 0 && gx < W)
                v = __ldg(src + imgBase + (long)gy * W + gx);
            sxy[r][c] = v;
        }
    }
    __syncthreads();

    phases345(sxy, pAB, p4, red, tx, ty, tid, sidx);
}

__global__ void finalize_kernel(float* __restrict__ out) {
    const double n0 = 64.0 * 512.0 * 512.0;
    const double n1 = 64.0 * 256.0 * 256.0;
    const double n2 = 64.0 * 128.0 * 128.0;
    double ms = 0.5 * (g_acc[0] / n0) + 0.3 * (g_acc[1] / n1) + 0.2 * (g_acc[2] / n2);
    out[0] = (float)(1.0 - ms);
    // reset for the next graph replay (globals start zeroed at module load)
    g_acc[0] = 0.0; g_acc[1] = 0.0; g_acc[2] = 0.0;
}

extern "C" void kernel_launch(void* const* d_in, const int* in_sizes, int n_in,
                              void* d_out, int out_size)
{
    const float* pred = (const float*)d_in[0];
    const float* targ = (const float*)d_in[1];
    float* out = (float*)d_out;

    dim3 blk(32, 8);
    ssim_scale0_kernel<<<dim3(16, 16, 64), blk>>>(pred, targ);
    ssim_small_kernel<<<dim3(8, 8, 80), blk>>>();
    finalize_kernel<<<1, 1>>>(out);
}

// round 6
// speedup vs baseline: 1.0929x; 1.0929x over previous
#include <cuda_runtime.h>
#include <cuda_bf16.h>

// ---------------------------------------------------------------------------
// MS-SSIM loss, 3 scales, 11x11 separable Gaussian (sigma=1.5), zero padding.
// R6: R4 phase structure (2-output items, 6 blocks/SM) + LDS.64 tap loads
//     (7 per item via x0-6 origin / SPITCH 44) + vectorized LDG.64 phase-1.
// ---------------------------------------------------------------------------

#define TILE   32
#define HALO   5
#define LDIM   42            // TILE + 2*HALO
#define SPITCH 44            // raw tile pitch (bf16x2 units), origin x0-6

__device__ constexpr float GWC[11] = {
    0.00102838f, 0.00759875f, 0.03600077f, 0.10936069f, 0.21300553f,
    0.26601173f, 0.21300553f, 0.10936069f, 0.03600077f, 0.00759875f,
    0.00102838f
};

#define C1_ 0.0001f
#define C2_ 0.0009f

typedef unsigned long long u64;

__device__ __forceinline__ u64 pack2(float a, float b) {
    u64 r; asm("mov.b64 %0, {%1, %2};" : "=l"(r) : "f"(a), "f"(b)); return r;
}
__device__ __forceinline__ void unpack2(u64 v, float& a, float& b) {
    asm("mov.b64 {%0, %1}, %2;" : "=f"(a), "=f"(b) : "l"(v));
}
__device__ __forceinline__ u64 fma2(u64 a, u64 b, u64 c) {
    u64 d; asm("fma.rn.f32x2 %0, %1, %2, %3;" : "=l"(d) : "l"(a), "l"(b), "l"(c)); return d;
}
__device__ __forceinline__ u64 mul2(u64 a, u64 b) {
    u64 d; asm("mul.rn.f32x2 %0, %1, %2;" : "=l"(d) : "l"(a), "l"(b)); return d;
}
// bf16x2 -> two fp32 via pure bit ops (exact)
__device__ __forceinline__ void bf2dec(unsigned v, float& a, float& b) {
    a = __int_as_float((int)(v << 16));
    b = __int_as_float((int)(v & 0xffff0000u));
}

// Pooled pyramids (allocation-free device globals), bf16x2 (pred, target)
__device__ __nv_bfloat162 g_s1[64 * 256 * 256];
__device__ __nv_bfloat162 g_s2[64 * 128 * 128];
__device__ double g_acc[3];   // zero-initialized at load; reset by finalize

// ---------------------------------------------------------------------------
// Phases 3-5. Tile x-origin is x0-6: output col c taps sxy cols c+1..c+11.
// Pair (c0, c0+1), c0 even: values sxy[c0+1 .. c0+12] from 7 LDS.64 covering
// cols c0..c0+13.
// ---------------------------------------------------------------------------
__device__ __forceinline__ void phases345(
    __nv_bfloat162 (&sxy)[LDIM][SPITCH],
    ulonglong2 (&pAB)[LDIM][TILE],
    float (&p4)[LDIM][TILE],
    float (&red)[8],
    int tx, int ty, int tid, int sidx)
{
    u64 wp[11];
    #pragma unroll
    for (int k = 0; k < 11; k++) wp[k] = pack2(GWC[k], GWC[k]);

    // ---- horizontal blur: 672 items x 2 outputs ----
    #pragma unroll
    for (int it = 0; it < 3; it++) {
        const int i = tid + it * 256;
        if (i < 672) {
            const int r  = i >> 4;
            const int c0 = (i & 15) * 2;
            const uint2* row64 = (const uint2*)&sxy[r][0];  // 8B-aligned rows
            uint2 raw[7];
            #pragma unroll
            for (int m = 0; m < 7; m++)
                raw[m] = row64[(c0 >> 1) + m];
            u64 hxy0 = 0, hsq0 = 0, hxy1 = 0, hsq1 = 0;
            float hab0 = 0.f, hab1 = 0.f;
            #pragma unroll
            for (int n = 1; n <= 12; n++) {
                unsigned v = (n & 1) ? raw[n >> 1].y : raw[n >> 1].x;
                float a, b; bf2dec(v, a, b);
                u64 p  = pack2(a, b);
                u64 sq = mul2(p, p);
                float ab = a * b;
                if (n <= 11) {            // out0: weight w[n-1]
                    hxy0 = fma2(p,  wp[n - 1], hxy0);
                    hsq0 = fma2(sq, wp[n - 1], hsq0);
                    hab0 = fmaf(ab, GWC[n - 1], hab0);
                }
                if (n >= 2) {             // out1: weight w[n-2]
                    hxy1 = fma2(p,  wp[n - 2], hxy1);
                    hsq1 = fma2(sq, wp[n - 2], hsq1);
                    hab1 = fmaf(ab, GWC[n - 2], hab1);
                }
            }
            pAB[r][c0]     = make_ulonglong2(hxy0, hsq0);
            pAB[r][c0 + 1] = make_ulonglong2(hxy1, hsq1);
            *(float2*)&p4[r][c0] = make_float2(hab0, hab1);
        }
    }
    __syncthreads();

    // ---- vertical blur + SSIM: 4 output rows per thread, 1 col ----
    u64   mA[4] = {0, 0, 0, 0};
    u64   mB[4] = {0, 0, 0, 0};
    float mC[4] = {0.f, 0.f, 0.f, 0.f};
    const int rbase = ty * 4;
    #pragma unroll
    for (int k = 0; k < 14; k++) {
        const int hr = rbase + k;
        ulonglong2 vab = pAB[hr][tx];          // LDS.128
        float v4 = p4[hr][tx];
        #pragma unroll
        for (int j = 0; j < 4; j++) {
            const int kk = k - j;
            if (kk >= 0 && kk < 11) {
                mA[j] = fma2(vab.x, wp[kk], mA[j]);
                mB[j] = fma2(vab.y, wp[kk], mB[j]);
                mC[j] = fmaf(v4, GWC[kk], mC[j]);
            }
        }
    }

    float acc = 0.0f;
    #pragma unroll
    for (int j = 0; j < 4; j++) {
        float mu1, mu2, exx, eyy;
        unpack2(mA[j], mu1, mu2);
        unpack2(mB[j], exx, eyy);
        float mu1sq = mu1 * mu1;
        float mu2sq = mu2 * mu2;
        float mu12  = mu1 * mu2;
        float s1  = exx - mu1sq;
        float s2  = eyy - mu2sq;
        float s12 = mC[j] - mu12;
        float num = (2.0f * mu12 + C1_) * (2.0f * s12 + C2_);
        float den = (mu1sq + mu2sq + C1_) * (s1 + s2 + C2_);
        acc += __fdividef(num, den);
    }

    #pragma unroll
    for (int o = 16; o > 0; o >>= 1)
        acc += __shfl_down_sync(0xffffffffu, acc, o);
    if ((tid & 31) == 0) red[tid >> 5] = acc;
    __syncthreads();
    if (tid < 8) {
        float v = red[tid];
        #pragma unroll
        for (int o = 4; o > 0; o >>= 1)
            v += __shfl_down_sync(0xffu, v, o, 8);
        if (tid == 0) atomicAdd(&g_acc[sidx], (double)v);
    }
}

// ---------------------------------------------------------------------------
// Scale 0: fp32 global inputs, writes BOTH pooled pyramids, then SSIM.
// ---------------------------------------------------------------------------
__global__ __launch_bounds__(256, 6)
void ssim_scale0_kernel(const float* __restrict__ pin, const float* __restrict__ tin)
{
    __shared__ __nv_bfloat162 sxy[LDIM][SPITCH];
    __shared__ ulonglong2 pAB[LDIM][TILE];
    __shared__ float p4[LDIM][TILE];
    __shared__ float red[8];

    const int tx = threadIdx.x, ty = threadIdx.y;
    const int tid = ty * 32 + tx;
    const int x0 = blockIdx.x * TILE;
    const int y0 = blockIdx.y * TILE;
    const int H = 512, W = 512;
    const long imgBase = (long)blockIdx.z * H * W;

    const bool interior = (x0 >= 8) && (x0 + 40 <= W) &&
                          (y0 >= 8) && (y0 + 40 <= H);
    if (interior) {
        // 42 rows x 22 float2 loads (x origin x0-6, 8B aligned)
        const float* pb = pin + imgBase + (long)(y0 - 5) * W + (x0 - 6);
        const float* tb = tin + imgBase + (long)(y0 - 5) * W + (x0 - 6);
        #pragma unroll
        for (int it = 0; it < 4; it++) {
            const int i = tid + it * 256;
            if (i < 924) {
                const int r = i / 22, c2 = i - r * 22;
                float2 av = __ldg((const float2*)(pb + (long)r * W) + c2);
                float2 bv = __ldg((const float2*)(tb + (long)r * W) + c2);
                __nv_bfloat162 t0 = __floats2bfloat162_rn(av.x, bv.x);
                __nv_bfloat162 t1 = __floats2bfloat162_rn(av.y, bv.y);
                *(uint2*)&sxy[r][2 * c2] =
                    make_uint2(*(unsigned*)&t0, *(unsigned*)&t1);
            }
        }
    } else {
        #pragma unroll
        for (int i = tid; i < LDIM * SPITCH; i += 256) {
            int r = i / SPITCH, c = i - r * SPITCH;
            int gy = y0 + r - 5;
            int gx = x0 + c - 6;
            float a = 0.0f, b = 0.0f;
            if (gy >= 0 && gy < H && gx >= 0 && gx < W) {
                long off = imgBase + (long)gy * W + gx;
                a = __ldg(pin + off);
                b = __ldg(tin + off);
            }
            sxy[r][c] = __floats2bfloat162_rn(a, b);
        }
    }
    __syncthreads();

    // 2x2 pool -> g_s1 (one output px per thread: 16x16)
    {
        const int pr = tid >> 4;
        const int pc = tid & 15;
        const int r = 5 + 2 * pr, c = 6 + 2 * pc;
        float a0, b0, a1, b1, a2, b2, a3, b3;
        bf2dec(*(const unsigned*)&sxy[r][c],         a0, b0);
        bf2dec(*(const unsigned*)&sxy[r][c + 1],     a1, b1);
        bf2dec(*(const unsigned*)&sxy[r + 1][c],     a2, b2);
        bf2dec(*(const unsigned*)&sxy[r + 1][c + 1], a3, b3);
        float a = 0.25f * (a0 + a1 + a2 + a3);
        float b = 0.25f * (b0 + b1 + b2 + b3);
        long poff = (long)blockIdx.z * 256 * 256
                  + (long)(y0 / 2 + pr) * 256 + (x0 / 2 + pc);
        g_s1[poff] = __floats2bfloat162_rn(a, b);
    }
    // 4x4 pool -> g_s2 (8x8 outputs per tile, threads 0..63)
    if (tid < 64) {
        const int pr = tid >> 3;
        const int pc = tid & 7;
        const int r = 5 + 4 * pr, c = 6 + 4 * pc;
        float sa = 0.f, sb = 0.f;
        #pragma unroll
        for (int dr = 0; dr < 4; dr++)
            #pragma unroll
            for (int dc = 0; dc < 4; dc++) {
                float a, b;
                bf2dec(*(const unsigned*)&sxy[r + dr][c + dc], a, b);
                sa += a; sb += b;
            }
        long poff = (long)blockIdx.z * 128 * 128
                  + (long)(y0 / 4 + pr) * 128 + (x0 / 4 + pc);
        g_s2[poff] = __floats2bfloat162_rn(sa * 0.0625f, sb * 0.0625f);
    }

    phases345(sxy, pAB, p4, red, tx, ty, tid, 0);
}

// ---------------------------------------------------------------------------
// Scales 1+2 merged: z < 64 -> scale1 (256x256), z >= 64 -> scale2 (128x128).
// ---------------------------------------------------------------------------
__global__ __launch_bounds__(256, 6)
void ssim_small_kernel()
{
    __shared__ __nv_bfloat162 sxy[LDIM][SPITCH];
    __shared__ ulonglong2 pAB[LDIM][TILE];
    __shared__ float p4[LDIM][TILE];
    __shared__ float red[8];

    const int tx = threadIdx.x, ty = threadIdx.y;
    const int tid = ty * 32 + tx;
    const int z = blockIdx.z;

    const __nv_bfloat162* src;
    int x0, y0, img, H, sidx;
    if (z < 64) {
        src = g_s1; H = 256; sidx = 1;
        x0 = blockIdx.x * TILE; y0 = blockIdx.y * TILE; img = z;
    } else {
        src = g_s2; H = 128; sidx = 2;
        const int z2 = z - 64;
        img = z2 * 4 + ((blockIdx.y >> 2) << 1) + (blockIdx.x >> 2);
        x0 = (blockIdx.x & 3) * TILE;
        y0 = (blockIdx.y & 3) * TILE;
    }
    const int W = H;
    const long imgBase = (long)img * H * W;

    const bool interior = (x0 >= 8) && (x0 + 40 <= W) &&
                          (y0 >= 8) && (y0 + 40 <= H);
    if (interior) {
        const __nv_bfloat162* sb = src + imgBase + (long)(y0 - 5) * W + (x0 - 6);
        #pragma unroll
        for (int it = 0; it < 4; it++) {
            const int i = tid + it * 256;
            if (i < 924) {
                const int r = i / 22, c2 = i - r * 22;
                uint2 v = __ldg((const uint2*)(sb + (long)r * W) + c2);
                *(uint2*)&sxy[r][2 * c2] = v;
            }
        }
    } else {
        #pragma unroll
        for (int i = tid; i < LDIM * SPITCH; i += 256) {
            int r = i / SPITCH, c = i - r * SPITCH;
            int gy = y0 + r - 5;
            int gx = x0 + c - 6;
            __nv_bfloat162 v; *(unsigned*)&v = 0u;
            if (gy >= 0 && gy < H && gx >= 0 && gx < W)
                v = __ldg(src + imgBase + (long)gy * W + gx);
            sxy[r][c] = v;
        }
    }
    __syncthreads();

    phases345(sxy, pAB, p4, red, tx, ty, tid, sidx);
}

__global__ void finalize_kernel(float* __restrict__ out) {
    const double n0 = 64.0 * 512.0 * 512.0;
    const double n1 = 64.0 * 256.0 * 256.0;
    const double n2 = 64.0 * 128.0 * 128.0;
    double ms = 0.5 * (g_acc[0] / n0) + 0.3 * (g_acc[1] / n1) + 0.2 * (g_acc[2] / n2);
    out[0] = (float)(1.0 - ms);
    // reset for the next graph replay (globals start zeroed at module load)
    g_acc[0] = 0.0; g_acc[1] = 0.0; g_acc[2] = 0.0;
}

extern "C" void kernel_launch(void* const* d_in, const int* in_sizes, int n_in,
                              void* d_out, int out_size)
{
    const float* pred = (const float*)d_in[0];
    const float* targ = (const float*)d_in[1];
    float* out = (float*)d_out;

    dim3 blk(32, 8);
    ssim_scale0_kernel<<<dim3(16, 16, 64), blk>>>(pred, targ);
    ssim_small_kernel<<<dim3(8, 8, 80), blk>>>();
    finalize_kernel<<<1, 1>>>(out);
}

// round 7
// speedup vs baseline: 1.2298x; 1.1252x over previous
#include <cuda_runtime.h>
#include <cuda_bf16.h>

// ---------------------------------------------------------------------------
// MS-SSIM loss, 3 scales, 11x11 separable Gaussian (sigma=1.5), zero padding.
// R7: (u,v) = (x+y, x-y) channel transform -> only 4 blur channels
//     (u, v, u^2, v^2), fully f32x2-packed; p4 plane eliminated; smem 29K,
//     7 blocks/SM target.
// ---------------------------------------------------------------------------

#define TILE   32
#define HALO   5
#define LDIM   42            // TILE + 2*HALO
#define SPITCH 44            // raw tile pitch (bf16x2 units), origin x0-6

__device__ constexpr float GWC[11] = {
    0.00102838f, 0.00759875f, 0.03600077f, 0.10936069f, 0.21300553f,
    0.26601173f, 0.21300553f, 0.10936069f, 0.03600077f, 0.00759875f,
    0.00102838f
};

#define C1_ 0.0001f
#define C2_ 0.0009f

typedef unsigned long long u64;

__device__ __forceinline__ u64 pack2(float a, float b) {
    u64 r; asm("mov.b64 %0, {%1, %2};" : "=l"(r) : "f"(a), "f"(b)); return r;
}
__device__ __forceinline__ void unpack2(u64 v, float& a, float& b) {
    asm("mov.b64 {%0, %1}, %2;" : "=f"(a), "=f"(b) : "l"(v));
}
__device__ __forceinline__ u64 fma2(u64 a, u64 b, u64 c) {
    u64 d; asm("fma.rn.f32x2 %0, %1, %2, %3;" : "=l"(d) : "l"(a), "l"(b), "l"(c)); return d;
}
__device__ __forceinline__ u64 mul2(u64 a, u64 b) {
    u64 d; asm("mul.rn.f32x2 %0, %1, %2;" : "=l"(d) : "l"(a), "l"(b)); return d;
}
// bf16x2 -> two fp32 via pure bit ops (exact)
__device__ __forceinline__ void bf2dec(unsigned v, float& a, float& b) {
    a = __int_as_float((int)(v << 16));
    b = __int_as_float((int)(v & 0xffff0000u));
}

// Pooled pyramids (device globals), bf16x2 storing (u, v) = (p+t, p-t)
__device__ __nv_bfloat162 g_s1[64 * 256 * 256];
__device__ __nv_bfloat162 g_s2[64 * 128 * 128];
__device__ double g_acc[3];   // zero-initialized at load; reset by finalize

// ---------------------------------------------------------------------------
// Phases 3-5. Tile x-origin is x0-6: output col c taps sxy cols c+1..c+11.
// Channels: A = blur(u,v) packed, B = blur(u^2,v^2) packed.
// ---------------------------------------------------------------------------
__device__ __forceinline__ void phases345(
    __nv_bfloat162 (&sxy)[LDIM][SPITCH],
    ulonglong2 (&pAB)[LDIM][TILE],
    float (&red)[8],
    int tx, int ty, int tid, int sidx)
{
    u64 wp[11];
    #pragma unroll
    for (int k = 0; k < 11; k++) wp[k] = pack2(GWC[k], GWC[k]);

    // ---- horizontal blur: 672 items x 2 outputs ----
    #pragma unroll
    for (int it = 0; it < 3; it++) {
        const int i = tid + it * 256;
        if (i < 672) {
            const int r  = i >> 4;
            const int c0 = (i & 15) * 2;
            const uint2* row64 = (const uint2*)&sxy[r][0];  // 8B-aligned rows
            uint2 raw[7];
            #pragma unroll
            for (int m = 0; m < 7; m++)
                raw[m] = row64[(c0 >> 1) + m];
            u64 hA0 = 0, hB0 = 0, hA1 = 0, hB1 = 0;
            #pragma unroll
            for (int n = 1; n <= 12; n++) {
                unsigned v = (n & 1) ? raw[n >> 1].y : raw[n >> 1].x;
                float a, b; bf2dec(v, a, b);
                u64 p  = pack2(a, b);
                u64 sq = mul2(p, p);
                if (n <= 11) {            // out0: weight w[n-1]
                    hA0 = fma2(p,  wp[n - 1], hA0);
                    hB0 = fma2(sq, wp[n - 1], hB0);
                }
                if (n >= 2) {             // out1: weight w[n-2]
                    hA1 = fma2(p,  wp[n - 2], hA1);
                    hB1 = fma2(sq, wp[n - 2], hB1);
                }
            }
            pAB[r][c0]     = make_ulonglong2(hA0, hB0);
            pAB[r][c0 + 1] = make_ulonglong2(hA1, hB1);
        }
    }
    __syncthreads();

    // ---- vertical blur + SSIM: 4 output rows per thread, 1 col ----
    u64 mA[4] = {0, 0, 0, 0};   // (mu_u, mu_v)
    u64 mB[4] = {0, 0, 0, 0};   // (E[u^2], E[v^2])
    const int rbase = ty * 4;
    #pragma unroll
    for (int k = 0; k < 14; k++) {
        const int hr = rbase + k;
        ulonglong2 vab = pAB[hr][tx];          // LDS.128
        #pragma unroll
        for (int j = 0; j < 4; j++) {
            const int kk = k - j;
            if (kk >= 0 && kk < 11) {
                mA[j] = fma2(vab.x, wp[kk], mA[j]);
                mB[j] = fma2(vab.y, wp[kk], mB[j]);
            }
        }
    }

    float acc = 0.0f;
    #pragma unroll
    for (int j = 0; j < 4; j++) {
        u64 m2 = mul2(mA[j], mA[j]);           // (mu_u^2, mu_v^2)
        float m2u, m2v; unpack2(m2, m2u, m2v);
        float eu, ev;   unpack2(mB[j], eu, ev);
        float D1 = m2u - m2v;                  // = 4*mu1*mu2
        float S1 = m2u + m2v;                  // = 2*(mu1^2+mu2^2)
        float DE = eu - ev;                    // = 4*E[xy]
        float SE = eu + ev;                    // = 2*(E[x^2]+E[y^2])
        float num = (0.5f * D1 + C1_) * (0.5f * (DE - D1) + C2_);
        float den = (0.5f * S1 + C1_) * (0.5f * (SE - S1) + C2_);
        acc += __fdividef(num, den);
    }

    #pragma unroll
    for (int o = 16; o > 0; o >>= 1)
        acc += __shfl_down_sync(0xffffffffu, acc, o);
    if ((tid & 31) == 0) red[tid >> 5] = acc;
    __syncthreads();
    if (tid < 8) {
        float v = red[tid];
        #pragma unroll
        for (int o = 4; o > 0; o >>= 1)
            v += __shfl_down_sync(0xffu, v, o, 8);
        if (tid == 0) atomicAdd(&g_acc[sidx], (double)v);
    }
}

// ---------------------------------------------------------------------------
// Scale 0: fp32 global inputs -> (u,v) bf16x2 tile; writes BOTH pooled
// pyramids (2x2 and 4x4, linear in (u,v)); then SSIM.
// ---------------------------------------------------------------------------
__global__ __launch_bounds__(256, 7)
void ssim_scale0_kernel(const float* __restrict__ pin, const float* __restrict__ tin)
{
    __shared__ __nv_bfloat162 sxy[LDIM][SPITCH];
    __shared__ ulonglong2 pAB[LDIM][TILE];
    __shared__ float red[8];

    const int tx = threadIdx.x, ty = threadIdx.y;
    const int tid = ty * 32 + tx;
    const int x0 = blockIdx.x * TILE;
    const int y0 = blockIdx.y * TILE;
    const int H = 512, W = 512;
    const long imgBase = (long)blockIdx.z * H * W;

    const bool interior = (x0 >= 8) && (x0 + 40 <= W) &&
                          (y0 >= 8) && (y0 + 40 <= H);
    if (interior) {
        // 42 rows x 22 float2 loads (x origin x0-6, 8B aligned)
        const float* pb = pin + imgBase + (long)(y0 - 5) * W + (x0 - 6);
        const float* tb = tin + imgBase + (long)(y0 - 5) * W + (x0 - 6);
        #pragma unroll
        for (int it = 0; it < 4; it++) {
            const int i = tid + it * 256;
            if (i < 924) {
                const int r = i / 22, c2 = i - r * 22;
                float2 av = __ldg((const float2*)(pb + (long)r * W) + c2);
                float2 bv = __ldg((const float2*)(tb + (long)r * W) + c2);
                __nv_bfloat162 t0 = __floats2bfloat162_rn(av.x + bv.x, av.x - bv.x);
                __nv_bfloat162 t1 = __floats2bfloat162_rn(av.y + bv.y, av.y - bv.y);
                *(uint2*)&sxy[r][2 * c2] =
                    make_uint2(*(unsigned*)&t0, *(unsigned*)&t1);
            }
        }
    } else {
        #pragma unroll
        for (int i = tid; i < LDIM * SPITCH; i += 256) {
            int r = i / SPITCH, c = i - r * SPITCH;
            int gy = y0 + r - 5;
            int gx = x0 + c - 6;
            float a = 0.0f, b = 0.0f;
            if (gy >= 0 && gy < H && gx >= 0 && gx < W) {
                long off = imgBase + (long)gy * W + gx;
                a = __ldg(pin + off);
                b = __ldg(tin + off);
            }
            sxy[r][c] = __floats2bfloat162_rn(a + b, a - b);
        }
    }
    __syncthreads();

    // 2x2 pool -> g_s1 (pooling is linear in (u,v))
    {
        const int pr = tid >> 4;
        const int pc = tid & 15;
        const int r = 5 + 2 * pr, c = 6 + 2 * pc;
        float u0, v0, u1, v1, u2, v2, u3, v3;
        bf2dec(*(const unsigned*)&sxy[r][c],         u0, v0);
        bf2dec(*(const unsigned*)&sxy[r][c + 1],     u1, v1);
        bf2dec(*(const unsigned*)&sxy[r + 1][c],     u2, v2);
        bf2dec(*(const unsigned*)&sxy[r + 1][c + 1], u3, v3);
        float u = 0.25f * (u0 + u1 + u2 + u3);
        float v = 0.25f * (v0 + v1 + v2 + v3);
        long poff = (long)blockIdx.z * 256 * 256
                  + (long)(y0 / 2 + pr) * 256 + (x0 / 2 + pc);
        g_s1[poff] = __floats2bfloat162_rn(u, v);
    }
    // 4x4 pool -> g_s2 (threads 0..63)
    if (tid < 64) {
        const int pr = tid >> 3;
        const int pc = tid & 7;
        const int r = 5 + 4 * pr, c = 6 + 4 * pc;
        float su = 0.f, sv = 0.f;
        #pragma unroll
        for (int dr = 0; dr < 4; dr++)
            #pragma unroll
            for (int dc = 0; dc < 4; dc++) {
                float u, v;
                bf2dec(*(const unsigned*)&sxy[r + dr][c + dc], u, v);
                su += u; sv += v;
            }
        long poff = (long)blockIdx.z * 128 * 128
                  + (long)(y0 / 4 + pr) * 128 + (x0 / 4 + pc);
        g_s2[poff] = __floats2bfloat162_rn(su * 0.0625f, sv * 0.0625f);
    }

    phases345(sxy, pAB, red, tx, ty, tid, 0);
}

// ---------------------------------------------------------------------------
// Scales 1+2 merged: z < 64 -> scale1 (256x256), z >= 64 -> scale2 (128x128).
// ---------------------------------------------------------------------------
__global__ __launch_bounds__(256, 7)
void ssim_small_kernel()
{
    __shared__ __nv_bfloat162 sxy[LDIM][SPITCH];
    __shared__ ulonglong2 pAB[LDIM][TILE];
    __shared__ float red[8];

    const int tx = threadIdx.x, ty = threadIdx.y;
    const int tid = ty * 32 + tx;
    const int z = blockIdx.z;

    const __nv_bfloat162* src;
    int x0, y0, img, H, sidx;
    if (z < 64) {
        src = g_s1; H = 256; sidx = 1;
        x0 = blockIdx.x * TILE; y0 = blockIdx.y * TILE; img = z;
    } else {
        src = g_s2; H = 128; sidx = 2;
        const int z2 = z - 64;
        img = z2 * 4 + ((blockIdx.y >> 2) << 1) + (blockIdx.x >> 2);
        x0 = (blockIdx.x & 3) * TILE;
        y0 = (blockIdx.y & 3) * TILE;
    }
    const int W = H;
    const long imgBase = (long)img * H * W;

    const bool interior = (x0 >= 8) && (x0 + 40 <= W) &&
                          (y0 >= 8) && (y0 + 40 <= H);
    if (interior) {
        const __nv_bfloat162* sb = src + imgBase + (long)(y0 - 5) * W + (x0 - 6);
        #pragma unroll
        for (int it = 0; it < 4; it++) {
            const int i = tid + it * 256;
            if (i < 924) {
                const int r = i / 22, c2 = i - r * 22;
                uint2 v = __ldg((const uint2*)(sb + (long)r * W) + c2);
                *(uint2*)&sxy[r][2 * c2] = v;
            }
        }
    } else {
        #pragma unroll
        for (int i = tid; i < LDIM * SPITCH; i += 256) {
            int r = i / SPITCH, c = i - r * SPITCH;
            int gy = y0 + r - 5;
            int gx = x0 + c - 6;
            __nv_bfloat162 v; *(unsigned*)&v = 0u;
            if (gy >= 0 && gy < H && gx >= 0 && gx < W)
                v = __ldg(src + imgBase + (long)gy * W + gx);
            sxy[r][c] = v;
        }
    }
    __syncthreads();

    phases345(sxy, pAB, red, tx, ty, tid, sidx);
}

__global__ void finalize_kernel(float* __restrict__ out) {
    const double n0 = 64.0 * 512.0 * 512.0;
    const double n1 = 64.0 * 256.0 * 256.0;
    const double n2 = 64.0 * 128.0 * 128.0;
    double ms = 0.5 * (g_acc[0] / n0) + 0.3 * (g_acc[1] / n1) + 0.2 * (g_acc[2] / n2);
    out[0] = (float)(1.0 - ms);
    // reset for the next graph replay (globals start zeroed at module load)
    g_acc[0] = 0.0; g_acc[1] = 0.0; g_acc[2] = 0.0;
}

extern "C" void kernel_launch(void* const* d_in, const int* in_sizes, int n_in,
                              void* d_out, int out_size)
{
    const float* pred = (const float*)d_in[0];
    const float* targ = (const float*)d_in[1];
    float* out = (float*)d_out;

    dim3 blk(32, 8);
    ssim_scale0_kernel<<<dim3(16, 16, 64), blk>>>(pred, targ);
    ssim_small_kernel<<<dim3(8, 8, 80), blk>>>();
    finalize_kernel<<<1, 1>>>(out);
}